// round 11
// baseline (speedup 1.0000x reference)
#include <cuda_runtime.h>
#include <cuda_fp16.h>
#include <cstdint>
#include <cstring>

// Problem constants (TMDLayer): B=8, N=2048, F=256, L=16, EPS=0.25
#define BB 8
#define NN 2048
#define FF 256
#define LL 16
#define EPSV 0.25f
#define NT 16          // K tiles of 128
#define NPAIRS 136
#define YTASKS 64      // y-tiles of 32 per batch
#define YTK 32
#define MTASKS 32      // main n-blocks of 64 per batch
#define TASKS_PER_B (NPAIRS + YTASKS + MTASKS)   // 232
#define NTASKS (TASKS_PER_B * BB)                // 1856
#define NL2E 1.4426950408889634f

typedef unsigned long long ull;

// ---------------- device scratch ----------------
__device__ __half g_zh[BB * NN * LL];
__device__ float g_sqh[BB * NN];
__device__ float g_pi[BB * NN];
__device__ float g_c[BB * NN];
__device__ float g_qpart[(size_t)BB * NT * NN];
__device__ __align__(128) __half g_K[(size_t)BB * NN * NN];   // [b][n][m]
__device__ __align__(128) __half g_y[(size_t)BB * FF * NN];   // [b][f][m]
// sync: [0]=taskCtr, [1+b]=kDone[b], [9+b]=yDone[b]
__device__ int g_sync[20];

// ---------------- helpers ----------------
__device__ __forceinline__ void grid_dep_wait() {
    asm volatile("griddepcontrol.wait;" ::: "memory");
}
__device__ __forceinline__ unsigned smem_u32(const void* p) {
    unsigned a;
    asm("{ .reg .u64 t; cvta.to.shared.u64 t, %1; cvt.u32.u64 %0, t; }" : "=r"(a) : "l"(p));
    return a;
}
__device__ __forceinline__ void cp_async16s(unsigned dst, const void* src) {
    asm volatile("cp.async.cg.shared.global [%0], [%1], 16;\n" :: "r"(dst), "l"(src));
}
__device__ __forceinline__ void cp_commit() { asm volatile("cp.async.commit_group;\n"); }
__device__ __forceinline__ void cp_wait0() { asm volatile("cp.async.wait_group 0;\n"); }
__device__ __forceinline__ void cp_wait1() { asm volatile("cp.async.wait_group 1;\n"); }
__device__ __forceinline__ void cp_wait2() { asm volatile("cp.async.wait_group 2;\n"); }

__device__ __forceinline__ ull ffma2(ull a, ull b, ull c) {
    ull d;
    asm("fma.rn.f32x2 %0, %1, %2, %3;" : "=l"(d) : "l"(a), "l"(b), "l"(c));
    return d;
}
union F2U { ull u; float2 f; };
__device__ __forceinline__ float hadd2(ull v) { F2U t; t.u = v; return t.f.x + t.f.y; }

__device__ __forceinline__ void mma16816(float* d, const uint32_t* a, const uint32_t* b) {
    asm volatile(
        "mma.sync.aligned.m16n8k16.row.col.f32.f16.f16.f32 "
        "{%0,%1,%2,%3}, {%4,%5,%6,%7}, {%8,%9}, {%0,%1,%2,%3};"
        : "+f"(d[0]), "+f"(d[1]), "+f"(d[2]), "+f"(d[3])
        : "r"(a[0]), "r"(a[1]), "r"(a[2]), "r"(a[3]), "r"(b[0]), "r"(b[1]));
}
__device__ __forceinline__ void ldsm4(uint32_t* r, unsigned addr) {
    asm volatile("ldmatrix.sync.aligned.m8n8.x4.shared.b16 {%0,%1,%2,%3}, [%4];"
        : "=r"(r[0]), "=r"(r[1]), "=r"(r[2]), "=r"(r[3]) : "r"(addr));
}
__device__ __forceinline__ uint32_t ex2_f16x2(uint32_t a) {
    uint32_t d;
    asm("ex2.approx.f16x2 %0, %1;" : "=r"(d) : "r"(a));
    return d;
}
__device__ __forceinline__ uint32_t movmat_t(uint32_t a) {
    uint32_t d;
    asm("movmatrix.sync.aligned.m8n8.trans.b16 %0, %1;" : "=r"(d) : "r"(a));
    return d;
}
__device__ __forceinline__ float h2sum(uint32_t h) {
    __half2 v = *reinterpret_cast<__half2*>(&h);
    float2 f = __half22float2(v);
    return f.x + f.y;
}
__device__ __forceinline__ void spin_geq(const int* p, int val) {
    int v;
    do {
        asm volatile("ld.global.acquire.gpu.b32 %0, [%1];" : "=r"(v) : "l"(p));
        if (v < val) __nanosleep(64);
    } while (v < val);
}

// =====================================================================
// Kernel 1 (separate launch): z, zh, sqh, pi.
// =====================================================================
__global__ void __launch_bounds__(256) k_zpi(const float* __restrict__ x,
                                             const float* __restrict__ pw,
                                             const float* __restrict__ pb,
                                             const float* __restrict__ w1,
                                             const float* __restrict__ b1,
                                             const float* __restrict__ w2,
                                             const float* __restrict__ b2) {
    __shared__ __align__(16) float xs[16][260];
    __shared__ __align__(16) float pws[16][260];
    __shared__ __align__(16) float zs[16][18];
    __shared__ float red[16][17];
    __shared__ __align__(16) float w1s[256][18];
    __shared__ float b1s[256];
    __shared__ float w2s[256];

    const int tid = threadIdx.x;
    const int p0 = blockIdx.x * 16;
    const float* xbase = x + (size_t)p0 * FF;

    for (int i = tid; i < 16 * 64; i += 256) {
        int r = i >> 6, c = (i & 63) << 2;
        float4 v = *reinterpret_cast<const float4*>(xbase + r * FF + c);
        *reinterpret_cast<float4*>(&xs[r][c]) = v;
    }
    for (int i = tid; i < LL * FF; i += 256) pws[i >> 8][i & 255] = pw[i];
    for (int i = tid; i < FF * LL; i += 256) w1s[i >> 4][i & 15] = w1[i];
    b1s[tid] = b1[tid];
    w2s[tid] = w2[tid];
    __syncthreads();

    const int n = tid >> 4;
    const int l = tid & 15;
    ull a0 = 0ULL, a1 = 0ULL, a2 = 0ULL, a3 = 0ULL;
#pragma unroll 8
    for (int f8 = 0; f8 < FF / 8; f8++) {
        const int base = f8 * 8;
        ulonglong2 xv0 = *reinterpret_cast<const ulonglong2*>(&xs[n][base]);
        ulonglong2 wv0 = *reinterpret_cast<const ulonglong2*>(&pws[l][base]);
        ulonglong2 xv1 = *reinterpret_cast<const ulonglong2*>(&xs[n][base + 4]);
        ulonglong2 wv1 = *reinterpret_cast<const ulonglong2*>(&pws[l][base + 4]);
        a0 = ffma2(xv0.x, wv0.x, a0);
        a1 = ffma2(xv0.y, wv0.y, a1);
        a2 = ffma2(xv1.x, wv1.x, a2);
        a3 = ffma2(xv1.y, wv1.y, a3);
    }
    float acc = (hadd2(a0) + hadd2(a1)) + (hadd2(a2) + hadd2(a3)) + pb[l];

    __half zh = __float2half_rn(acc);
    g_zh[(size_t)(p0 + n) * LL + l] = zh;
    float az = __half2float(zh);
    zs[n][l] = acc;
    red[n][l] = az * az;
    __syncthreads();
    if (l == 0) {
        float s = 0.f;
#pragma unroll
        for (int j = 0; j < LL; j++) s += red[n][j];
        g_sqh[p0 + n] = s;
    }

    ull zp[8];
#pragma unroll
    for (int l2 = 0; l2 < 8; l2++) zp[l2] = *reinterpret_cast<const ull*>(&zs[n][l2 << 1]);

    float accum = 0.f;
#pragma unroll 4
    for (int i = 0; i < 16; i++) {
        const int f = l + 16 * i;
        ull d2 = 0ULL;
#pragma unroll
        for (int l2 = 0; l2 < 8; l2++) {
            ull wv = *reinterpret_cast<const ull*>(&w1s[f][l2 << 1]);
            d2 = ffma2(zp[l2], wv, d2);
        }
        float hv = hadd2(d2) + b1s[f];
        hv = fmaxf(hv, 0.f);
        accum = fmaf(hv, w2s[f], accum);
    }
#pragma unroll
    for (int o = 8; o > 0; o >>= 1) accum += __shfl_down_sync(0xffffffffu, accum, o, 16);
    if (l == 0) {
        float t = accum + b2[0];
        g_pi[p0 + n] = 1.0f / (1.0f + __expf(-t));
    }
}

// =====================================================================
// Fused persistent kernel: phases K / y / main as tasks.
// =====================================================================
// K-phase smem offsets (within shared buffer)
#define GPW 12
#define KPW 68
#define KTPH 136
#define O_ZN  0u
#define O_ZM  6144u
#define O_SQN 12288u
#define O_SQM 12800u
#define O_KT  13312u
#define O_KTT 48128u
#define O_RS  82944u
#define O_CS  83456u
// main-phase smem offsets
#define KAPITCH 40
#define ABYTES3 (64 * 80)
#define BBYTES3 (256 * 80)
#define STAGE (ABYTES3 + BBYTES3)
#define NSTAGE 4
#define KTILES 64
#define OFF_C3  (NSTAGE * STAGE)
#define OFF_RS3 (OFF_C3 + 512)
#define OFF_SC3 (OFF_RS3 + 1024)
#define SMEMF   (OFF_SC3 + 256)       // 104192

__device__ __forceinline__ void do_K(int b, int p, unsigned char* ks) {
    uint32_t* znW = reinterpret_cast<uint32_t*>(ks + O_ZN);
    uint32_t* zmW = reinterpret_cast<uint32_t*>(ks + O_ZM);
    float* sqnS = reinterpret_cast<float*>(ks + O_SQN);
    float* sqmS = reinterpret_cast<float*>(ks + O_SQM);
    uint32_t* ktW = reinterpret_cast<uint32_t*>(ks + O_KT);
    __half* ktT = reinterpret_cast<__half*>(ks + O_KTT);
    float* rsS = reinterpret_cast<float*>(ks + O_RS);
    float (*csS)[132] = reinterpret_cast<float(*)[132]>(ks + O_CS);

    const int tid = threadIdx.x;
    int ti = 0;
    while (p >= NT - ti) { p -= NT - ti; ti++; }
    const int tj = ti + p;
    const bool diag = (ti == tj);

    {
        const uint32_t* gn = reinterpret_cast<const uint32_t*>(
            g_zh + ((size_t)b * NN + ti * 128) * LL);
        const uint32_t* gm = reinterpret_cast<const uint32_t*>(
            g_zh + ((size_t)b * NN + tj * 128) * LL);
        for (int i = tid; i < 1024; i += 256) {
            znW[(i >> 3) * GPW + (i & 7)] = gn[i];
            zmW[(i >> 3) * GPW + (i & 7)] = gm[i];
        }
        const float* sqb = g_sqh + (size_t)b * NN;
        if (tid < 128) {
            sqnS[tid] = -NL2E * sqb[ti * 128 + tid];
            sqmS[tid] = -NL2E * sqb[tj * 128 + tid];
        }
    }
    __syncthreads();

    const int w = tid >> 5, lane = tid & 31;
    const int g = lane >> 2, q = lane & 3;
    const int r0 = w * 16 + g, r1 = r0 + 8;

    uint32_t af[4];
    af[0] = znW[r0 * GPW + q];
    af[1] = znW[r1 * GPW + q];
    af[2] = znW[r0 * GPW + q + 4];
    af[3] = znW[r1 * GPW + q + 4];

    const float sqr0 = sqnS[r0], sqr1 = sqnS[r1];
    const float TWOL2E = 2.0f * NL2E;
    float rs0 = 0.f, rs1 = 0.f;
#pragma unroll 4
    for (int cf = 0; cf < 16; cf++) {
        float acc[4];
        acc[0] = acc[1] = acc[2] = acc[3] = 0.f;
        uint32_t bf[2];
        bf[0] = zmW[(cf * 8 + g) * GPW + q];
        bf[1] = zmW[(cf * 8 + g) * GPW + q + 4];
        mma16816(acc, af, bf);

        const int c0 = cf * 8 + 2 * q;
        float2 sqc = *reinterpret_cast<const float2*>(&sqmS[c0]);
        float t00 = fminf(fmaf(TWOL2E, acc[0], sqr0 + sqc.x), 0.f);
        float t01 = fminf(fmaf(TWOL2E, acc[1], sqr0 + sqc.y), 0.f);
        float t10 = fminf(fmaf(TWOL2E, acc[2], sqr1 + sqc.x), 0.f);
        float t11 = fminf(fmaf(TWOL2E, acc[3], sqr1 + sqc.y), 0.f);
        __half2 e0 = __floats2half2_rn(t00, t01);
        __half2 e1 = __floats2half2_rn(t10, t11);
        uint32_t h0 = ex2_f16x2(*reinterpret_cast<uint32_t*>(&e0));
        uint32_t h1 = ex2_f16x2(*reinterpret_cast<uint32_t*>(&e1));

        rs0 += h2sum(h0);
        rs1 += h2sum(h1);

        ktW[r0 * KPW + (c0 >> 1)] = h0;
        ktW[r1 * KPW + (c0 >> 1)] = h1;

        if (!diag) {
            uint32_t h0t = movmat_t(h0);
            uint32_t h1t = movmat_t(h1);
            *reinterpret_cast<uint32_t*>(&ktT[(cf * 8 + g) * KTPH + w * 16 + 2 * q]) = h0t;
            *reinterpret_cast<uint32_t*>(&ktT[(cf * 8 + g) * KTPH + w * 16 + 8 + 2 * q]) = h1t;
            float cp = h2sum(h0t) + h2sum(h1t);
            cp += __shfl_xor_sync(0xffffffffu, cp, 1);
            cp += __shfl_xor_sync(0xffffffffu, cp, 2);
            if (q == 0) csS[w][cf * 8 + g] = cp;
        }
    }
    rs0 += __shfl_xor_sync(0xffffffffu, rs0, 1);
    rs0 += __shfl_xor_sync(0xffffffffu, rs0, 2);
    rs1 += __shfl_xor_sync(0xffffffffu, rs1, 1);
    rs1 += __shfl_xor_sync(0xffffffffu, rs1, 2);
    if (q == 0) { rsS[r0] = rs0; rsS[r1] = rs1; }
    __syncthreads();

    if (tid < 128)
        g_qpart[((size_t)b * NT + tj) * NN + ti * 128 + tid] = rsS[tid];
    if (!diag && tid < 128) {
        float s = 0.f;
#pragma unroll
        for (int ww = 0; ww < 8; ww++) s += csS[ww][tid];
        g_qpart[((size_t)b * NT + ti) * NN + tj * 128 + tid] = s;
    }

    {
        float4* gK1 = reinterpret_cast<float4*>(
            g_K + ((size_t)(b * NN + ti * 128)) * NN + tj * 128);
        for (int i = tid; i < 2048; i += 256) {
            const int r = i >> 4, j = i & 15;
            gK1[(size_t)r * (NN / 8) + j] =
                *reinterpret_cast<const float4*>(ktW + r * KPW + 4 * j);
        }
        if (!diag) {
            float4* gK2 = reinterpret_cast<float4*>(
                g_K + ((size_t)(b * NN + tj * 128)) * NN + ti * 128);
            const uint32_t* ktTW = reinterpret_cast<const uint32_t*>(ktT);
            for (int i = tid; i < 2048; i += 256) {
                const int r = i >> 4, j = i & 15;
                gK2[(size_t)r * (NN / 8) + j] =
                    *reinterpret_cast<const float4*>(ktTW + r * KPW + 4 * j);
            }
        }
    }
}

__device__ __forceinline__ void do_y(int b, int mt, unsigned char* ks,
                                     const float* __restrict__ x) {
    float* cs = reinterpret_cast<float*>(ks);                         // 128 B
    uint32_t (*yt)[17] = reinterpret_cast<uint32_t(*)[17]>(ks + 128); // 17408 B

    const int tid = threadIdx.x;
    const float* xb = x + ((size_t)b * NN + mt * YTK) * FF;

    if (tid < YTK) {
        const int lm = mt * YTK + tid;
        float q = 0.f;
#pragma unroll
        for (int s = 0; s < NT; s++) q += g_qpart[((size_t)b * NT + s) * NN + lm];
        float c = g_pi[b * NN + lm] / q;
        g_c[b * NN + lm] = c;
        cs[tid] = c;
    }
    __syncthreads();

    const int f = tid;
#pragma unroll 8
    for (int j = 0; j < 16; j++) {
        float y0 = cs[2 * j]     * __ldg(xb + (size_t)(2 * j) * FF + f);
        float y1 = cs[2 * j + 1] * __ldg(xb + (size_t)(2 * j + 1) * FF + f);
        __half2 hv = __floats2half2_rn(y0, y1);
        yt[f][j] = *reinterpret_cast<uint32_t*>(&hv);
    }
    __syncthreads();
    uint32_t* gY = reinterpret_cast<uint32_t*>(g_y + ((size_t)b * FF * NN + mt * YTK));
    for (int i = tid; i < 256 * 16; i += 256)
        gY[(size_t)(i >> 4) * (NN / 2) + (i & 15)] = yt[i >> 4][i & 15];
}

__device__ __forceinline__ void do_main(int b, int nb, unsigned char* sm, unsigned smb,
                                        const float* __restrict__ x,
                                        float* __restrict__ out,
                                        const float* __restrict__ dtp) {
    const int tid = threadIdx.x;
    const int wid = tid >> 5, lane = tid & 31;
    const int g = lane >> 2, q = lane & 3;
    const int wm = wid & 1, wn = wid >> 1;

    const __half* Kg = g_K + (size_t)(b * NN + nb * 64) * NN;
    const __half* Yg = g_y + (size_t)b * FF * NN;
    const float* cg = g_c + (size_t)b * NN;

    auto fill = [&](int t, int st) {
        const unsigned aS = smb + st * STAGE;
        const unsigned bS = aS + ABYTES3;
        const __half* aG = Kg + t * 32;
        const __half* bG = Yg + t * 32;
        {
            const int i = tid;
            cp_async16s(aS + (i >> 2) * 80 + (i & 3) * 16,
                        aG + (size_t)(i >> 2) * NN + (i & 3) * 8);
        }
        for (int i = tid; i < 1024; i += 256)
            cp_async16s(bS + (i >> 2) * 80 + (i & 3) * 16,
                        bG + (size_t)(i >> 2) * NN + (i & 3) * 8);
        if (tid < 8)
            cp_async16s(smb + OFF_C3 + st * 128 + tid * 16, cg + t * 32 + tid * 4);
        cp_commit();
    };

    fill(0, 0);
    fill(1, 1);
    fill(2, 2);

    float acc[2][8][4];
#pragma unroll
    for (int mf = 0; mf < 2; mf++)
#pragma unroll
        for (int nf = 0; nf < 8; nf++)
#pragma unroll
            for (int k = 0; k < 4; k++) acc[mf][nf][k] = 0.f;
    float rs = 0.f;
    const int rn = tid & 63, qm = tid >> 6;

    const int a_row = wm * 32 + (lane & 15);
    const int a_kof = (lane >> 4) << 3;
    const int b_row = wn * 64 + (lane & 7) + ((lane >> 4) << 3);
    const int b_kof = ((lane >> 3) & 1) << 3;

    for (int t = 0; t < KTILES; t++) {
        const int st = t & 3;
        const int rem = KTILES - 1 - t;
        if (rem >= 2) cp_wait2(); else if (rem == 1) cp_wait1(); else cp_wait0();
        __syncthreads();
        if (t + 3 < KTILES) fill(t + 3, (t + 3) & 3);

        const unsigned KsA = smb + st * STAGE;
        const unsigned YsA = KsA + ABYTES3;
        const __half* Ks = reinterpret_cast<const __half*>(sm + st * STAGE);

        {
            const float* cP = reinterpret_cast<const float*>(sm + OFF_C3 + st * 128);
#pragma unroll
            for (int j = 0; j < 4; j++) {
                __half2 hv = *reinterpret_cast<const __half2*>(Ks + rn * KAPITCH + qm * 8 + 2 * j);
                float2 fv = __half22float2(hv);
                rs = fmaf(fv.x, cP[qm * 8 + 2 * j], rs);
                rs = fmaf(fv.y, cP[qm * 8 + 2 * j + 1], rs);
            }
        }

#pragma unroll
        for (int ksI = 0; ksI < 2; ksI++) {
            const int k0 = ksI * 16;
            uint32_t af[2][4];
#pragma unroll
            for (int mf = 0; mf < 2; mf++)
                ldsm4(af[mf], KsA + ((a_row + mf * 16) * KAPITCH + k0 + a_kof) * 2);
            uint32_t bf[8][2];
#pragma unroll
            for (int np = 0; np < 4; np++) {
                uint32_t r4[4];
                ldsm4(r4, YsA + ((b_row + np * 16) * KAPITCH + k0 + b_kof) * 2);
                bf[np * 2][0] = r4[0]; bf[np * 2][1] = r4[1];
                bf[np * 2 + 1][0] = r4[2]; bf[np * 2 + 1][1] = r4[3];
            }
#pragma unroll
            for (int mf = 0; mf < 2; mf++)
#pragma unroll
                for (int nf = 0; nf < 8; nf++)
                    mma16816(acc[mf][nf], af[mf], bf[nf]);
        }
    }

    __syncthreads();
    reinterpret_cast<float*>(sm + OFF_RS3)[rn * 4 + qm] = rs;
    __syncthreads();
    const float dtv = dtp[0];
    if (tid < 64) {
        const float* rp = reinterpret_cast<const float*>(sm + OFF_RS3) + tid * 4;
        float row = rp[0] + rp[1] + rp[2] + rp[3] + 1e-5f;
        reinterpret_cast<float*>(sm + OFF_SC3)[tid] = (dtv / EPSV) / row;
    }
    __syncthreads();

    const float omdt = 1.0f - dtv;
    const float* scS = reinterpret_cast<const float*>(sm + OFF_SC3);
#pragma unroll
    for (int mf = 0; mf < 2; mf++) {
        const int lr = wm * 32 + mf * 16 + g;
        const float sc1 = scS[lr], sc2 = scS[lr + 8];
        const size_t r1 = (size_t)(b * NN + nb * 64 + lr) * FF;
        const size_t r2 = r1 + (size_t)8 * FF;
#pragma unroll
        for (int nf = 0; nf < 8; nf++) {
            const int col = wn * 64 + nf * 8 + 2 * q;
            float2 x1 = *reinterpret_cast<const float2*>(x + r1 + col);
            float2 x2 = *reinterpret_cast<const float2*>(x + r2 + col);
            float2 o1, o2;
            o1.x = omdt * x1.x + sc1 * acc[mf][nf][0];
            o1.y = omdt * x1.y + sc1 * acc[mf][nf][1];
            o2.x = omdt * x2.x + sc2 * acc[mf][nf][2];
            o2.y = omdt * x2.y + sc2 * acc[mf][nf][3];
            *reinterpret_cast<float2*>(out + r1 + col) = o1;
            *reinterpret_cast<float2*>(out + r2 + col) = o2;
        }
    }
}

__global__ void __launch_bounds__(256, 2)
k_fused(const float* __restrict__ x, float* __restrict__ out,
        const float* __restrict__ dtp) {
    extern __shared__ __align__(16) unsigned char sm[];
    const unsigned smb = smem_u32(sm);
    const int tid = threadIdx.x;
    __shared__ int curTask;

    grid_dep_wait();

    while (true) {
        __syncthreads();                     // smem + curTask reuse barrier
        if (tid == 0) curTask = atomicAdd(&g_sync[0], 1);
        __syncthreads();
        const int t = curTask;
        if (t >= NTASKS) break;
        const int b = t / TASKS_PER_B;
        const int r = t - b * TASKS_PER_B;

        if (r < NPAIRS) {
            do_K(b, r, sm);
            __syncthreads();
            if (tid == 0) { __threadfence(); atomicAdd(&g_sync[1 + b], 1); }
        } else if (r < NPAIRS + YTASKS) {
            if (tid == 0) spin_geq(&g_sync[1 + b], NPAIRS);
            __syncthreads();
            do_y(b, r - NPAIRS, sm, x);
            __syncthreads();
            if (tid == 0) { __threadfence(); atomicAdd(&g_sync[9 + b], 1); }
        } else {
            if (tid == 0) {
                spin_geq(&g_sync[1 + b], NPAIRS);
                spin_geq(&g_sync[9 + b], YTASKS);
            }
            __syncthreads();
            do_main(b, r - (NPAIRS + YTASKS), sm, smb, x, out, dtp);
        }
    }
}

// =====================================================================
// launch: memset(sync) -> k_zpi -> PDL -> k_fused (persistent scheduler)
// =====================================================================
extern "C" void kernel_launch(void* const* d_in, const int* in_sizes, int n_in,
                              void* d_out, int out_size) {
    const float* x  = (const float*)d_in[0];
    const float* pw = (const float*)d_in[1];
    const float* pb = (const float*)d_in[2];
    const float* w1 = (const float*)d_in[3];
    const float* b1 = (const float*)d_in[4];
    const float* w2 = (const float*)d_in[5];
    const float* b2 = (const float*)d_in[6];
    const float* dt = (const float*)d_in[7];
    float* out = (float*)d_out;

    (void)in_sizes; (void)n_in; (void)out_size;

    cudaFuncSetAttribute(k_fused, cudaFuncAttributeMaxDynamicSharedMemorySize, (int)SMEMF);

    // zero the scheduler counters (captured into the graph)
    void* syncAddr = nullptr;
    cudaGetSymbolAddress(&syncAddr, g_sync);
    cudaMemsetAsync(syncAddr, 0, sizeof(int) * 20, 0);

    k_zpi<<<(BB * NN) / 16, 256>>>(x, pw, pb, w1, b1, w2, b2);

    // persistent worker grid: 2 CTAs/SM (safe for any actual residency)
    int dev = 0, nsm = 148;
    cudaGetDevice(&dev);
    cudaDeviceGetAttribute(&nsm, cudaDevAttrMultiProcessorCount, dev);

    cudaLaunchAttribute at[1];
    at[0].id = cudaLaunchAttributeProgrammaticStreamSerialization;
    at[0].val.programmaticStreamSerializationAllowed = 1;

    cudaLaunchConfig_t cfg;
    memset(&cfg, 0, sizeof(cfg));
    cfg.blockDim = dim3(256, 1, 1);
    cfg.gridDim = dim3(2 * nsm, 1, 1);
    cfg.dynamicSmemBytes = SMEMF;
    cfg.attrs = at;
    cfg.numAttrs = 1;
    cfg.stream = 0;
    cudaLaunchKernelEx(&cfg, k_fused, x, out, dt);
}

// round 12
// speedup vs baseline: 1.4632x; 1.4632x over previous
#include <cuda_runtime.h>
#include <cuda_fp16.h>
#include <cstdint>
#include <cstring>

// Problem constants (TMDLayer): B=8, N=2048, F=256, L=16, EPS=0.25
#define BB 8
#define NN 2048
#define FF 256
#define LL 16
#define EPSV 0.25f
#define YT 64          // k_y m-tiles of 32
#define YTK 32
#define NT 16          // K tiles of 128
#define NPAIRS 136
#define NL2E 1.4426950408889634f

typedef unsigned long long ull;

// ---------------- device scratch ----------------
__device__ __half g_zh[BB * NN * LL];
__device__ float g_sqh[BB * NN];
__device__ float g_pi[BB * NN];
__device__ float g_c[BB * NN];
__device__ float g_qpart[(size_t)BB * NT * NN];
__device__ __align__(128) __half g_K[(size_t)BB * NN * NN];   // [b][n][m]
__device__ __align__(128) __half g_y[(size_t)BB * FF * NN];   // [b][f][m]

// ---------------- helpers ----------------
__device__ __forceinline__ void grid_dep_wait() {
    asm volatile("griddepcontrol.wait;" ::: "memory");
}
__device__ __forceinline__ unsigned smem_u32(const void* p) {
    unsigned a;
    asm("{ .reg .u64 t; cvta.to.shared.u64 t, %1; cvt.u32.u64 %0, t; }" : "=r"(a) : "l"(p));
    return a;
}
__device__ __forceinline__ void cp_async16s(unsigned dst, const void* src) {
    asm volatile("cp.async.cg.shared.global [%0], [%1], 16;\n" :: "r"(dst), "l"(src));
}
__device__ __forceinline__ void cp_commit() { asm volatile("cp.async.commit_group;\n"); }
__device__ __forceinline__ void cp_wait0() { asm volatile("cp.async.wait_group 0;\n"); }
__device__ __forceinline__ void cp_wait1() { asm volatile("cp.async.wait_group 1;\n"); }

__device__ __forceinline__ ull ffma2(ull a, ull b, ull c) {
    ull d;
    asm("fma.rn.f32x2 %0, %1, %2, %3;" : "=l"(d) : "l"(a), "l"(b), "l"(c));
    return d;
}
union F2U { ull u; float2 f; };
__device__ __forceinline__ float hadd2(ull v) { F2U t; t.u = v; return t.f.x + t.f.y; }

__device__ __forceinline__ void mma16816(float* d, const uint32_t* a, const uint32_t* b) {
    asm volatile(
        "mma.sync.aligned.m16n8k16.row.col.f32.f16.f16.f32 "
        "{%0,%1,%2,%3}, {%4,%5,%6,%7}, {%8,%9}, {%0,%1,%2,%3};"
        : "+f"(d[0]), "+f"(d[1]), "+f"(d[2]), "+f"(d[3])
        : "r"(a[0]), "r"(a[1]), "r"(a[2]), "r"(a[3]), "r"(b[0]), "r"(b[1]));
}
__device__ __forceinline__ void ldsm4(uint32_t* r, unsigned addr) {
    asm volatile("ldmatrix.sync.aligned.m8n8.x4.shared.b16 {%0,%1,%2,%3}, [%4];"
        : "=r"(r[0]), "=r"(r[1]), "=r"(r[2]), "=r"(r[3]) : "r"(addr));
}
__device__ __forceinline__ uint32_t ex2_f16x2(uint32_t a) {
    uint32_t d;
    asm("ex2.approx.f16x2 %0, %1;" : "=r"(d) : "r"(a));
    return d;
}
__device__ __forceinline__ uint32_t movmat_t(uint32_t a) {
    uint32_t d;
    asm("movmatrix.sync.aligned.m8n8.trans.b16 %0, %1;" : "=r"(d) : "r"(a));
    return d;
}
__device__ __forceinline__ float h2sum(uint32_t h) {
    __half2 v = *reinterpret_cast<__half2*>(&h);
    float2 f = __half22float2(v);
    return f.x + f.y;
}

// =====================================================================
// Kernel 1 (fused): z, zh, sqh, pi.
// =====================================================================
__global__ void __launch_bounds__(256) k_zpi(const float* __restrict__ x,
                                             const float* __restrict__ pw,
                                             const float* __restrict__ pb,
                                             const float* __restrict__ w1,
                                             const float* __restrict__ b1,
                                             const float* __restrict__ w2,
                                             const float* __restrict__ b2) {
    __shared__ __align__(16) float xs[16][260];
    __shared__ __align__(16) float pws[16][260];
    __shared__ __align__(16) float zs[16][18];
    __shared__ float red[16][17];
    __shared__ __align__(16) float w1s[256][18];
    __shared__ float b1s[256];
    __shared__ float w2s[256];

    const int tid = threadIdx.x;
    const int p0 = blockIdx.x * 16;
    const float* xbase = x + (size_t)p0 * FF;

    for (int i = tid; i < 16 * 64; i += 256) {
        int r = i >> 6, c = (i & 63) << 2;
        float4 v = *reinterpret_cast<const float4*>(xbase + r * FF + c);
        *reinterpret_cast<float4*>(&xs[r][c]) = v;
    }
    for (int i = tid; i < LL * FF; i += 256) pws[i >> 8][i & 255] = pw[i];
    for (int i = tid; i < FF * LL; i += 256) w1s[i >> 4][i & 15] = w1[i];
    b1s[tid] = b1[tid];
    w2s[tid] = w2[tid];
    __syncthreads();

    const int n = tid >> 4;
    const int l = tid & 15;
    ull a0 = 0ULL, a1 = 0ULL, a2 = 0ULL, a3 = 0ULL;
#pragma unroll 8
    for (int f8 = 0; f8 < FF / 8; f8++) {
        const int base = f8 * 8;
        ulonglong2 xv0 = *reinterpret_cast<const ulonglong2*>(&xs[n][base]);
        ulonglong2 wv0 = *reinterpret_cast<const ulonglong2*>(&pws[l][base]);
        ulonglong2 xv1 = *reinterpret_cast<const ulonglong2*>(&xs[n][base + 4]);
        ulonglong2 wv1 = *reinterpret_cast<const ulonglong2*>(&pws[l][base + 4]);
        a0 = ffma2(xv0.x, wv0.x, a0);
        a1 = ffma2(xv0.y, wv0.y, a1);
        a2 = ffma2(xv1.x, wv1.x, a2);
        a3 = ffma2(xv1.y, wv1.y, a3);
    }
    float acc = (hadd2(a0) + hadd2(a1)) + (hadd2(a2) + hadd2(a3)) + pb[l];

    __half zh = __float2half_rn(acc);
    g_zh[(size_t)(p0 + n) * LL + l] = zh;
    float az = __half2float(zh);
    zs[n][l] = acc;
    red[n][l] = az * az;
    __syncthreads();
    if (l == 0) {
        float s = 0.f;
#pragma unroll
        for (int j = 0; j < LL; j++) s += red[n][j];
        g_sqh[p0 + n] = s;
    }

    ull zp[8];
#pragma unroll
    for (int l2 = 0; l2 < 8; l2++) zp[l2] = *reinterpret_cast<const ull*>(&zs[n][l2 << 1]);

    float accum = 0.f;
#pragma unroll 4
    for (int i = 0; i < 16; i++) {
        const int f = l + 16 * i;
        ull d2 = 0ULL;
#pragma unroll
        for (int l2 = 0; l2 < 8; l2++) {
            ull wv = *reinterpret_cast<const ull*>(&w1s[f][l2 << 1]);
            d2 = ffma2(zp[l2], wv, d2);
        }
        float hv = hadd2(d2) + b1s[f];
        hv = fmaxf(hv, 0.f);
        accum = fmaf(hv, w2s[f], accum);
    }
#pragma unroll
    for (int o = 8; o > 0; o >>= 1) accum += __shfl_down_sync(0xffffffffu, accum, o, 16);
    if (l == 0) {
        float t = accum + b2[0];
        g_pi[p0 + n] = 1.0f / (1.0f + __expf(-t));
    }
}

// =====================================================================
// Kernel 2: symmetric K pass via HMMA Gram + wide fp16 ex2 (R10 proven).
// =====================================================================
#define GPW 12
#define KPW 68
#define KTPH 136
#define O_ZN  0u
#define O_ZM  6144u
#define O_SQN 12288u
#define O_SQM 12800u
#define O_KT  13312u
#define O_KTT 48128u
#define O_RS  82944u
#define O_CS  83456u
#define KK_SMEM 87680u

__global__ void __launch_bounds__(256, 2) k_K(void) {
    extern __shared__ __align__(16) unsigned char ks[];
    uint32_t* znW = reinterpret_cast<uint32_t*>(ks + O_ZN);
    uint32_t* zmW = reinterpret_cast<uint32_t*>(ks + O_ZM);
    float* sqnS = reinterpret_cast<float*>(ks + O_SQN);
    float* sqmS = reinterpret_cast<float*>(ks + O_SQM);
    uint32_t* ktW = reinterpret_cast<uint32_t*>(ks + O_KT);
    __half* ktT = reinterpret_cast<__half*>(ks + O_KTT);
    float* rsS = reinterpret_cast<float*>(ks + O_RS);
    float (*csS)[132] = reinterpret_cast<float(*)[132]>(ks + O_CS);

    const int tid = threadIdx.x;
    const int b = blockIdx.y;
    int p = blockIdx.x, ti = 0;
    while (p >= NT - ti) { p -= NT - ti; ti++; }
    const int tj = ti + p;
    const bool diag = (ti == tj);

    grid_dep_wait();

    {
        const uint32_t* gn = reinterpret_cast<const uint32_t*>(
            g_zh + ((size_t)b * NN + ti * 128) * LL);
        const uint32_t* gm = reinterpret_cast<const uint32_t*>(
            g_zh + ((size_t)b * NN + tj * 128) * LL);
        for (int i = tid; i < 1024; i += 256) {
            znW[(i >> 3) * GPW + (i & 7)] = gn[i];
            zmW[(i >> 3) * GPW + (i & 7)] = gm[i];
        }
        const float* sqb = g_sqh + (size_t)b * NN;
        if (tid < 128) {
            sqnS[tid] = -NL2E * sqb[ti * 128 + tid];
            sqmS[tid] = -NL2E * sqb[tj * 128 + tid];
        }
    }
    __syncthreads();

    const int w = tid >> 5, lane = tid & 31;
    const int g = lane >> 2, q = lane & 3;
    const int r0 = w * 16 + g, r1 = r0 + 8;

    uint32_t af[4];
    af[0] = znW[r0 * GPW + q];
    af[1] = znW[r1 * GPW + q];
    af[2] = znW[r0 * GPW + q + 4];
    af[3] = znW[r1 * GPW + q + 4];

    const float sqr0 = sqnS[r0], sqr1 = sqnS[r1];
    const float TWOL2E = 2.0f * NL2E;
    float rs0 = 0.f, rs1 = 0.f;
#pragma unroll 4
    for (int cf = 0; cf < 16; cf++) {
        float acc[4];
        acc[0] = acc[1] = acc[2] = acc[3] = 0.f;
        uint32_t bf[2];
        bf[0] = zmW[(cf * 8 + g) * GPW + q];
        bf[1] = zmW[(cf * 8 + g) * GPW + q + 4];
        mma16816(acc, af, bf);

        const int c0 = cf * 8 + 2 * q;
        float2 sqc = *reinterpret_cast<const float2*>(&sqmS[c0]);
        float t00 = fminf(fmaf(TWOL2E, acc[0], sqr0 + sqc.x), 0.f);
        float t01 = fminf(fmaf(TWOL2E, acc[1], sqr0 + sqc.y), 0.f);
        float t10 = fminf(fmaf(TWOL2E, acc[2], sqr1 + sqc.x), 0.f);
        float t11 = fminf(fmaf(TWOL2E, acc[3], sqr1 + sqc.y), 0.f);
        __half2 e0 = __floats2half2_rn(t00, t01);
        __half2 e1 = __floats2half2_rn(t10, t11);
        uint32_t h0 = ex2_f16x2(*reinterpret_cast<uint32_t*>(&e0));
        uint32_t h1 = ex2_f16x2(*reinterpret_cast<uint32_t*>(&e1));

        rs0 += h2sum(h0);
        rs1 += h2sum(h1);

        ktW[r0 * KPW + (c0 >> 1)] = h0;
        ktW[r1 * KPW + (c0 >> 1)] = h1;

        if (!diag) {
            uint32_t h0t = movmat_t(h0);
            uint32_t h1t = movmat_t(h1);
            *reinterpret_cast<uint32_t*>(&ktT[(cf * 8 + g) * KTPH + w * 16 + 2 * q]) = h0t;
            *reinterpret_cast<uint32_t*>(&ktT[(cf * 8 + g) * KTPH + w * 16 + 8 + 2 * q]) = h1t;
            float cp = h2sum(h0t) + h2sum(h1t);
            cp += __shfl_xor_sync(0xffffffffu, cp, 1);
            cp += __shfl_xor_sync(0xffffffffu, cp, 2);
            if (q == 0) csS[w][cf * 8 + g] = cp;
        }
    }
    rs0 += __shfl_xor_sync(0xffffffffu, rs0, 1);
    rs0 += __shfl_xor_sync(0xffffffffu, rs0, 2);
    rs1 += __shfl_xor_sync(0xffffffffu, rs1, 1);
    rs1 += __shfl_xor_sync(0xffffffffu, rs1, 2);
    if (q == 0) { rsS[r0] = rs0; rsS[r1] = rs1; }
    __syncthreads();

    if (tid < 128)
        g_qpart[((size_t)b * NT + tj) * NN + ti * 128 + tid] = rsS[tid];
    if (!diag && tid < 128) {
        float s = 0.f;
#pragma unroll
        for (int ww = 0; ww < 8; ww++) s += csS[ww][tid];
        g_qpart[((size_t)b * NT + ti) * NN + tj * 128 + tid] = s;
    }

    {
        float4* gK1 = reinterpret_cast<float4*>(
            g_K + ((size_t)(b * NN + ti * 128)) * NN + tj * 128);
        for (int i = tid; i < 2048; i += 256) {
            const int r = i >> 4, j = i & 15;
            gK1[(size_t)r * (NN / 8) + j] =
                *reinterpret_cast<const float4*>(ktW + r * KPW + 4 * j);
        }
        if (!diag) {
            float4* gK2 = reinterpret_cast<float4*>(
                g_K + ((size_t)(b * NN + tj * 128)) * NN + ti * 128);
            const uint32_t* ktTW = reinterpret_cast<const uint32_t*>(ktT);
            for (int i = tid; i < 2048; i += 256) {
                const int r = i >> 4, j = i & 15;
                gK2[(size_t)r * (NN / 8) + j] =
                    *reinterpret_cast<const float4*>(ktTW + r * KPW + 4 * j);
            }
        }
    }
}

// =====================================================================
// Kernel 3: q = sum partials ; c = pi/q ; y[f][m] = c[m]*x[m][f] fp16.
// =====================================================================
__global__ void __launch_bounds__(256) k_y(const float* __restrict__ x) {
    __shared__ float cs[YTK];
    __shared__ uint32_t yt[256][17];

    const int tid = threadIdx.x;
    const int mt = blockIdx.x, b = blockIdx.y;

    grid_dep_wait();

    const float* xb = x + ((size_t)b * NN + mt * YTK) * FF;

    if (tid < YTK) {
        const int lm = mt * YTK + tid;
        float q = 0.f;
#pragma unroll
        for (int s = 0; s < NT; s++) q += g_qpart[((size_t)b * NT + s) * NN + lm];
        float c = g_pi[b * NN + lm] / q;
        g_c[b * NN + lm] = c;
        cs[tid] = c;
    }
    __syncthreads();

    const int f = tid;
#pragma unroll 8
    for (int j = 0; j < 16; j++) {
        float y0 = cs[2 * j]     * __ldg(xb + (size_t)(2 * j) * FF + f);
        float y1 = cs[2 * j + 1] * __ldg(xb + (size_t)(2 * j + 1) * FF + f);
        __half2 hv = __floats2half2_rn(y0, y1);
        yt[f][j] = *reinterpret_cast<uint32_t*>(&hv);
    }
    __syncthreads();
    uint32_t* gY = reinterpret_cast<uint32_t*>(g_y + ((size_t)b * FF * NN + mt * YTK));
    for (int i = tid; i < 256 * 16; i += 256)
        gY[(size_t)(i >> 4) * (NN / 2) + (i & 15)] = yt[i >> 4][i & 15];
}

// =====================================================================
// Kernel 4: HMMA GEMM, CTA tile 128x256, warp tile 64x64 (occ 1).
// 3-stage cp.async, k-tile 32. Grid (16, 8). PDL-dependent on k_y.
// =====================================================================
#define KAPITCH 40                     // halves per row (80 B)
#define ABYTES4 (128 * 80)             // 10240
#define BBYTES4 (256 * 80)             // 20480
#define STAGE4 (ABYTES4 + BBYTES4)     // 30720
#define NSTAGE4 3
#define KTILES 64
#define OFF_C4  (NSTAGE4 * STAGE4)     // 92160: 3 x 32 floats
#define OFF_RS4 (OFF_C4 + 384)         // 92544: 128 x 2 floats
#define OFF_SC4 (OFF_RS4 + 1024)       // 93568: 128 floats
#define SMEM4   (OFF_SC4 + 512)        // 94080

__global__ void __launch_bounds__(256, 1)
k_main(const float* __restrict__ x, float* __restrict__ out,
       const float* __restrict__ dtp) {
    extern __shared__ __align__(16) unsigned char sm[];
    const unsigned smb = smem_u32(sm);

    const int tid = threadIdx.x;
    const int nb = blockIdx.x, b = blockIdx.y;
    const int wid = tid >> 5, lane = tid & 31;
    const int g = lane >> 2, q = lane & 3;
    const int wm = wid & 1, wn = wid >> 1;    // 2 m-warps x 4 n-warps

    const __half* Kg = g_K + (size_t)(b * NN + nb * 128) * NN;
    const __half* Yg = g_y + (size_t)b * FF * NN;
    const float* cg = g_c + (size_t)b * NN;

    grid_dep_wait();

    auto fill = [&](int t, int st) {
        const unsigned aS = smb + st * STAGE4;
        const unsigned bS = aS + ABYTES4;
        const __half* aG = Kg + t * 32;
        const __half* bG = Yg + t * 32;
        for (int i = tid; i < 512; i += 256)
            cp_async16s(aS + (i >> 2) * 80 + (i & 3) * 16,
                        aG + (size_t)(i >> 2) * NN + (i & 3) * 8);
        for (int i = tid; i < 1024; i += 256)
            cp_async16s(bS + (i >> 2) * 80 + (i & 3) * 16,
                        bG + (size_t)(i >> 2) * NN + (i & 3) * 8);
        if (tid < 8)
            cp_async16s(smb + OFF_C4 + st * 128 + tid * 16, cg + t * 32 + tid * 4);
        cp_commit();
    };

    fill(0, 0);
    fill(1, 1);

    float acc[4][8][4];
#pragma unroll
    for (int mf = 0; mf < 4; mf++)
#pragma unroll
        for (int nf = 0; nf < 8; nf++)
#pragma unroll
            for (int k = 0; k < 4; k++) acc[mf][nf][k] = 0.f;
    float rs = 0.f;
    const int rn = tid & 127, qm = tid >> 7;   // rowsum: 128 rows x 2 k-halves

    const int a_row = wm * 64 + (lane & 15);
    const int a_kof = (lane >> 4) << 3;
    const int b_row = wn * 64 + (lane & 7) + ((lane >> 4) << 3);
    const int b_kof = ((lane >> 3) & 1) << 3;

    for (int t = 0; t < KTILES; t++) {
        const int st = t % NSTAGE4;
        if (t < KTILES - 1) cp_wait1(); else cp_wait0();
        __syncthreads();
        if (t + 2 < KTILES) fill(t + 2, (t + 2) % NSTAGE4);

        const unsigned KsA = smb + st * STAGE4;
        const unsigned YsA = KsA + ABYTES4;
        const __half* Ks = reinterpret_cast<const __half*>(sm + st * STAGE4);

        // rowsum partial: thread (rn, qm) covers 16 m of this 32-k tile
        {
            const float* cP = reinterpret_cast<const float*>(sm + OFF_C4 + st * 128);
#pragma unroll
            for (int j = 0; j < 8; j++) {
                __half2 hv = *reinterpret_cast<const __half2*>(Ks + rn * KAPITCH + qm * 16 + 2 * j);
                float2 fv = __half22float2(hv);
                rs = fmaf(fv.x, cP[qm * 16 + 2 * j], rs);
                rs = fmaf(fv.y, cP[qm * 16 + 2 * j + 1], rs);
            }
        }

#pragma unroll
        for (int ksI = 0; ksI < 2; ksI++) {
            const int k0 = ksI * 16;
            uint32_t af[4][4];
#pragma unroll
            for (int mf = 0; mf < 4; mf++)
                ldsm4(af[mf], KsA + ((a_row + mf * 16) * KAPITCH + k0 + a_kof) * 2);
            uint32_t bf[8][2];
#pragma unroll
            for (int np = 0; np < 4; np++) {
                uint32_t r4[4];
                ldsm4(r4, YsA + ((b_row + np * 16) * KAPITCH + k0 + b_kof) * 2);
                bf[np * 2][0] = r4[0]; bf[np * 2][1] = r4[1];
                bf[np * 2 + 1][0] = r4[2]; bf[np * 2 + 1][1] = r4[3];
            }
#pragma unroll
            for (int mf = 0; mf < 4; mf++)
#pragma unroll
                for (int nf = 0; nf < 8; nf++)
                    mma16816(acc[mf][nf], af[mf], bf[nf]);
        }
    }

    __syncthreads();
    reinterpret_cast<float*>(sm + OFF_RS4)[rn * 2 + qm] = rs;
    __syncthreads();
    const float dtv = dtp[0];
    if (tid < 128) {
        const float* rp = reinterpret_cast<const float*>(sm + OFF_RS4) + tid * 2;
        float row = rp[0] + rp[1] + 1e-5f;
        reinterpret_cast<float*>(sm + OFF_SC4)[tid] = (dtv / EPSV) / row;
    }
    __syncthreads();

    const float omdt = 1.0f - dtv;
    const float* scS = reinterpret_cast<const float*>(sm + OFF_SC4);
#pragma unroll
    for (int mf = 0; mf < 4; mf++) {
        const int lr = wm * 64 + mf * 16 + g;
        const float sc1 = scS[lr], sc2 = scS[lr + 8];
        const size_t r1 = (size_t)(b * NN + nb * 128 + lr) * FF;
        const size_t r2 = r1 + (size_t)8 * FF;
#pragma unroll
        for (int nf = 0; nf < 8; nf++) {
            const int col = wn * 64 + nf * 8 + 2 * q;
            float2 x1 = *reinterpret_cast<const float2*>(x + r1 + col);
            float2 x2 = *reinterpret_cast<const float2*>(x + r2 + col);
            float2 o1, o2;
            o1.x = omdt * x1.x + sc1 * acc[mf][nf][0];
            o1.y = omdt * x1.y + sc1 * acc[mf][nf][1];
            o2.x = omdt * x2.x + sc2 * acc[mf][nf][2];
            o2.y = omdt * x2.y + sc2 * acc[mf][nf][3];
            *reinterpret_cast<float2*>(out + r1 + col) = o1;
            *reinterpret_cast<float2*>(out + r2 + col) = o2;
        }
    }
}

// =====================================================================
// launch — PDL chain: k_zpi -> k_K -> k_y -> k_main
// =====================================================================
extern "C" void kernel_launch(void* const* d_in, const int* in_sizes, int n_in,
                              void* d_out, int out_size) {
    const float* x  = (const float*)d_in[0];
    const float* pw = (const float*)d_in[1];
    const float* pb = (const float*)d_in[2];
    const float* w1 = (const float*)d_in[3];
    const float* b1 = (const float*)d_in[4];
    const float* w2 = (const float*)d_in[5];
    const float* b2 = (const float*)d_in[6];
    const float* dt = (const float*)d_in[7];
    float* out = (float*)d_out;

    (void)in_sizes; (void)n_in; (void)out_size;

    const int npts = BB * NN;

    cudaFuncSetAttribute(k_K, cudaFuncAttributeMaxDynamicSharedMemorySize, (int)KK_SMEM);
    cudaFuncSetAttribute(k_main, cudaFuncAttributeMaxDynamicSharedMemorySize, (int)SMEM4);

    k_zpi<<<npts / 16, 256>>>(x, pw, pb, w1, b1, w2, b2);

    cudaLaunchAttribute at[1];
    at[0].id = cudaLaunchAttributeProgrammaticStreamSerialization;
    at[0].val.programmaticStreamSerializationAllowed = 1;

    cudaLaunchConfig_t cfg;
    memset(&cfg, 0, sizeof(cfg));
    cfg.blockDim = dim3(256, 1, 1);
    cfg.attrs = at;
    cfg.numAttrs = 1;
    cfg.stream = 0;

    cfg.gridDim = dim3(NPAIRS, BB, 1);
    cfg.dynamicSmemBytes = KK_SMEM;
    cudaLaunchKernelEx(&cfg, k_K);

    cfg.gridDim = dim3(YT, BB, 1);
    cfg.dynamicSmemBytes = 0;
    cudaLaunchKernelEx(&cfg, k_y, x);

    cfg.gridDim = dim3(NN / 128, BB, 1);
    cfg.dynamicSmemBytes = SMEM4;
    cudaLaunchKernelEx(&cfg, k_main, x, out, dt);
}

// round 13
// speedup vs baseline: 1.6703x; 1.1416x over previous
#include <cuda_runtime.h>
#include <cuda_fp16.h>
#include <cstdint>
#include <cstring>

// Problem constants (TMDLayer): B=8, N=2048, F=256, L=16, EPS=0.25
#define BB 8
#define NN 2048
#define FF 256
#define LL 16
#define EPSV 0.25f
#define YT 64          // k_y m-tiles of 32
#define YTK 32
#define NT 16          // K tiles of 128
#define NPAIRS 136
#define NL2E 1.4426950408889634f

typedef unsigned long long ull;

// ---------------- device scratch ----------------
__device__ __half g_zh[BB * NN * LL];
__device__ float g_sqs[BB * NN];              // -log2e * |zh|^2 (pre-scaled)
__device__ float g_pi[BB * NN];
__device__ float g_c[BB * NN];
__device__ float g_qpart[(size_t)BB * NT * NN];
__device__ __align__(128) __half g_y[(size_t)BB * FF * NN];   // [b][f][m]

// ---------------- helpers ----------------
__device__ __forceinline__ void grid_dep_wait() {
    asm volatile("griddepcontrol.wait;" ::: "memory");
}
__device__ __forceinline__ unsigned smem_u32(const void* p) {
    unsigned a;
    asm("{ .reg .u64 t; cvta.to.shared.u64 t, %1; cvt.u32.u64 %0, t; }" : "=r"(a) : "l"(p));
    return a;
}
__device__ __forceinline__ void cp_async16s(unsigned dst, const void* src) {
    asm volatile("cp.async.cg.shared.global [%0], [%1], 16;\n" :: "r"(dst), "l"(src));
}
__device__ __forceinline__ void cp_commit() { asm volatile("cp.async.commit_group;\n"); }
__device__ __forceinline__ void cp_wait0() { asm volatile("cp.async.wait_group 0;\n"); }
__device__ __forceinline__ void cp_wait1() { asm volatile("cp.async.wait_group 1;\n"); }

__device__ __forceinline__ ull ffma2(ull a, ull b, ull c) {
    ull d;
    asm("fma.rn.f32x2 %0, %1, %2, %3;" : "=l"(d) : "l"(a), "l"(b), "l"(c));
    return d;
}
union F2U { ull u; float2 f; };
__device__ __forceinline__ float hadd2(ull v) { F2U t; t.u = v; return t.f.x + t.f.y; }

__device__ __forceinline__ void mma16816(float* d, const uint32_t* a, const uint32_t* b) {
    asm volatile(
        "mma.sync.aligned.m16n8k16.row.col.f32.f16.f16.f32 "
        "{%0,%1,%2,%3}, {%4,%5,%6,%7}, {%8,%9}, {%0,%1,%2,%3};"
        : "+f"(d[0]), "+f"(d[1]), "+f"(d[2]), "+f"(d[3])
        : "r"(a[0]), "r"(a[1]), "r"(a[2]), "r"(a[3]), "r"(b[0]), "r"(b[1]));
}
__device__ __forceinline__ void ldsm4(uint32_t* r, unsigned addr) {
    asm volatile("ldmatrix.sync.aligned.m8n8.x4.shared.b16 {%0,%1,%2,%3}, [%4];"
        : "=r"(r[0]), "=r"(r[1]), "=r"(r[2]), "=r"(r[3]) : "r"(addr));
}
__device__ __forceinline__ uint32_t ex2_f16x2(uint32_t a) {
    uint32_t d;
    asm("ex2.approx.f16x2 %0, %1;" : "=r"(d) : "r"(a));
    return d;
}
__device__ __forceinline__ uint32_t movmat_t(uint32_t a) {
    uint32_t d;
    asm("movmatrix.sync.aligned.m8n8.trans.b16 %0, %1;" : "=r"(d) : "r"(a));
    return d;
}
__device__ __forceinline__ float h2sum(uint32_t h) {
    __half2 v = *reinterpret_cast<__half2*>(&h);
    float2 f = __half22float2(v);
    return f.x + f.y;
}
__device__ __forceinline__ uint32_t packh2(float a, float b) {
    __half2 h = __floats2half2_rn(a, b);
    return *reinterpret_cast<uint32_t*>(&h);
}

// =====================================================================
// Kernel 1 (fused): z, zh, sqs = -log2e*|zh|^2, pi.
// =====================================================================
__global__ void __launch_bounds__(256) k_zpi(const float* __restrict__ x,
                                             const float* __restrict__ pw,
                                             const float* __restrict__ pb,
                                             const float* __restrict__ w1,
                                             const float* __restrict__ b1,
                                             const float* __restrict__ w2,
                                             const float* __restrict__ b2) {
    __shared__ __align__(16) float xs[16][260];
    __shared__ __align__(16) float pws[16][260];
    __shared__ __align__(16) float zs[16][18];
    __shared__ float red[16][17];
    __shared__ __align__(16) float w1s[256][18];
    __shared__ float b1s[256];
    __shared__ float w2s[256];

    const int tid = threadIdx.x;
    const int p0 = blockIdx.x * 16;
    const float* xbase = x + (size_t)p0 * FF;

    for (int i = tid; i < 16 * 64; i += 256) {
        int r = i >> 6, c = (i & 63) << 2;
        float4 v = *reinterpret_cast<const float4*>(xbase + r * FF + c);
        *reinterpret_cast<float4*>(&xs[r][c]) = v;
    }
    for (int i = tid; i < LL * FF; i += 256) pws[i >> 8][i & 255] = pw[i];
    for (int i = tid; i < FF * LL; i += 256) w1s[i >> 4][i & 15] = w1[i];
    b1s[tid] = b1[tid];
    w2s[tid] = w2[tid];
    __syncthreads();

    const int n = tid >> 4;
    const int l = tid & 15;
    ull a0 = 0ULL, a1 = 0ULL, a2 = 0ULL, a3 = 0ULL;
#pragma unroll 8
    for (int f8 = 0; f8 < FF / 8; f8++) {
        const int base = f8 * 8;
        ulonglong2 xv0 = *reinterpret_cast<const ulonglong2*>(&xs[n][base]);
        ulonglong2 wv0 = *reinterpret_cast<const ulonglong2*>(&pws[l][base]);
        ulonglong2 xv1 = *reinterpret_cast<const ulonglong2*>(&xs[n][base + 4]);
        ulonglong2 wv1 = *reinterpret_cast<const ulonglong2*>(&pws[l][base + 4]);
        a0 = ffma2(xv0.x, wv0.x, a0);
        a1 = ffma2(xv0.y, wv0.y, a1);
        a2 = ffma2(xv1.x, wv1.x, a2);
        a3 = ffma2(xv1.y, wv1.y, a3);
    }
    float acc = (hadd2(a0) + hadd2(a1)) + (hadd2(a2) + hadd2(a3)) + pb[l];

    __half zh = __float2half_rn(acc);
    g_zh[(size_t)(p0 + n) * LL + l] = zh;
    float az = __half2float(zh);
    zs[n][l] = acc;
    red[n][l] = az * az;
    __syncthreads();
    if (l == 0) {
        float s = 0.f;
#pragma unroll
        for (int j = 0; j < LL; j++) s += red[n][j];
        g_sqs[p0 + n] = -NL2E * s;
    }

    ull zp[8];
#pragma unroll
    for (int l2 = 0; l2 < 8; l2++) zp[l2] = *reinterpret_cast<const ull*>(&zs[n][l2 << 1]);

    float accum = 0.f;
#pragma unroll 4
    for (int i = 0; i < 16; i++) {
        const int f = l + 16 * i;
        ull d2 = 0ULL;
#pragma unroll
        for (int l2 = 0; l2 < 8; l2++) {
            ull wv = *reinterpret_cast<const ull*>(&w1s[f][l2 << 1]);
            d2 = ffma2(zp[l2], wv, d2);
        }
        float hv = hadd2(d2) + b1s[f];
        hv = fmaxf(hv, 0.f);
        accum = fmaf(hv, w2s[f], accum);
    }
#pragma unroll
    for (int o = 8; o > 0; o >>= 1) accum += __shfl_down_sync(0xffffffffu, accum, o, 16);
    if (l == 0) {
        float t = accum + b2[0];
        g_pi[p0 + n] = 1.0f / (1.0f + __expf(-t));
    }
}

// =====================================================================
// Kernel 2: q pass only (no K stores). Gram HMMA + ex2 + row/col sums.
// Symmetric tile pairs. Grid (NPAIRS, BB).
// =====================================================================
#define GPW 12

__global__ void __launch_bounds__(256) k_q(void) {
    __shared__ __align__(16) uint32_t znW[128 * GPW];
    __shared__ __align__(16) uint32_t zmW[128 * GPW];
    __shared__ float sqnS[128], sqmS[128];
    __shared__ float rsS[128];
    __shared__ float csS[8][132];

    const int tid = threadIdx.x;
    const int b = blockIdx.y;
    int p = blockIdx.x, ti = 0;
    while (p >= NT - ti) { p -= NT - ti; ti++; }
    const int tj = ti + p;
    const bool diag = (ti == tj);

    grid_dep_wait();

    {
        const uint32_t* gn = reinterpret_cast<const uint32_t*>(
            g_zh + ((size_t)b * NN + ti * 128) * LL);
        const uint32_t* gm = reinterpret_cast<const uint32_t*>(
            g_zh + ((size_t)b * NN + tj * 128) * LL);
        for (int i = tid; i < 1024; i += 256) {
            znW[(i >> 3) * GPW + (i & 7)] = gn[i];
            zmW[(i >> 3) * GPW + (i & 7)] = gm[i];
        }
        const float* sqb = g_sqs + (size_t)b * NN;
        if (tid < 128) {
            sqnS[tid] = sqb[ti * 128 + tid];
            sqmS[tid] = sqb[tj * 128 + tid];
        }
    }
    __syncthreads();

    const int w = tid >> 5, lane = tid & 31;
    const int g = lane >> 2, q = lane & 3;
    const int r0 = w * 16 + g, r1 = r0 + 8;

    uint32_t af[4];
    af[0] = znW[r0 * GPW + q];
    af[1] = znW[r1 * GPW + q];
    af[2] = znW[r0 * GPW + q + 4];
    af[3] = znW[r1 * GPW + q + 4];

    const float sqr0 = sqnS[r0], sqr1 = sqnS[r1];
    const float TWOL2E = 2.0f * NL2E;
    float rs0 = 0.f, rs1 = 0.f;
#pragma unroll 4
    for (int cf = 0; cf < 16; cf++) {
        float acc[4];
        acc[0] = acc[1] = acc[2] = acc[3] = 0.f;
        uint32_t bf[2];
        bf[0] = zmW[(cf * 8 + g) * GPW + q];
        bf[1] = zmW[(cf * 8 + g) * GPW + q + 4];
        mma16816(acc, af, bf);

        const int c0 = cf * 8 + 2 * q;
        float2 sqc = *reinterpret_cast<const float2*>(&sqmS[c0]);
        uint32_t h0 = ex2_f16x2(packh2(
            fminf(fmaf(TWOL2E, acc[0], sqr0 + sqc.x), 0.f),
            fminf(fmaf(TWOL2E, acc[1], sqr0 + sqc.y), 0.f)));
        uint32_t h1 = ex2_f16x2(packh2(
            fminf(fmaf(TWOL2E, acc[2], sqr1 + sqc.x), 0.f),
            fminf(fmaf(TWOL2E, acc[3], sqr1 + sqc.y), 0.f)));

        rs0 += h2sum(h0);
        rs1 += h2sum(h1);

        if (!diag) {
            float cp = h2sum(movmat_t(h0)) + h2sum(movmat_t(h1));
            cp += __shfl_xor_sync(0xffffffffu, cp, 1);
            cp += __shfl_xor_sync(0xffffffffu, cp, 2);
            if (q == 0) csS[w][cf * 8 + g] = cp;
        }
    }
    rs0 += __shfl_xor_sync(0xffffffffu, rs0, 1);
    rs0 += __shfl_xor_sync(0xffffffffu, rs0, 2);
    rs1 += __shfl_xor_sync(0xffffffffu, rs1, 1);
    rs1 += __shfl_xor_sync(0xffffffffu, rs1, 2);
    if (q == 0) { rsS[r0] = rs0; rsS[r1] = rs1; }
    __syncthreads();

    if (tid < 128)
        g_qpart[((size_t)b * NT + tj) * NN + ti * 128 + tid] = rsS[tid];
    if (!diag && tid < 128) {
        float s = 0.f;
#pragma unroll
        for (int ww = 0; ww < 8; ww++) s += csS[ww][tid];
        g_qpart[((size_t)b * NT + ti) * NN + tj * 128 + tid] = s;
    }
}

// =====================================================================
// Kernel 3: q = sum partials ; c = pi/q ; y[f][m] = c[m]*x[m][f] fp16.
// =====================================================================
__global__ void __launch_bounds__(256) k_y(const float* __restrict__ x) {
    __shared__ float cs[YTK];
    __shared__ uint32_t yt[256][17];

    const int tid = threadIdx.x;
    const int mt = blockIdx.x, b = blockIdx.y;

    grid_dep_wait();

    const float* xb = x + ((size_t)b * NN + mt * YTK) * FF;

    if (tid < YTK) {
        const int lm = mt * YTK + tid;
        float q = 0.f;
#pragma unroll
        for (int s = 0; s < NT; s++) q += g_qpart[((size_t)b * NT + s) * NN + lm];
        float c = g_pi[b * NN + lm] / q;
        g_c[b * NN + lm] = c;
        cs[tid] = c;
    }
    __syncthreads();

    const int f = tid;
#pragma unroll 8
    for (int j = 0; j < 16; j++) {
        float y0 = cs[2 * j]     * __ldg(xb + (size_t)(2 * j) * FF + f);
        float y1 = cs[2 * j + 1] * __ldg(xb + (size_t)(2 * j + 1) * FF + f);
        yt[f][j] = packh2(y0, y1);
    }
    __syncthreads();
    uint32_t* gY = reinterpret_cast<uint32_t*>(g_y + ((size_t)b * FF * NN + mt * YTK));
    for (int i = tid; i < 256 * 16; i += 256)
        gY[(size_t)(i >> 4) * (NN / 2) + (i & 15)] = yt[i >> 4][i & 15];
}

// =====================================================================
// Kernel 4 (fused flash-style): K recomputed in registers per m-tile.
// CTA: 128 rows x 256 cols. Warp w owns rows w*16..+15, all 256 cols.
// Per tile (m=32): Gram MMA (zn x zm) -> d2 -> ex2 -> A-frags -> main MMA.
// 3-stage cp.async for y/zm/c/sq tiles. Grid (16, 8).
// =====================================================================
#define KAPITCH 40                        // y pitch in halves (80B)
#define YB 20480                          // 256*80
#define ZMB 1536                          // 32*48
#define CSB 256                           // 32 c + 32 sq floats
#define ST4 (YB + ZMB + CSB)              // 22272
#define NST 3
#define KTILES 64
#define OFF_ZN (NST * ST4)                // 66816
#define ZNB (128 * 48)                    // 6144
#define OFF_RS (OFF_ZN + ZNB)             // 72960
#define OFF_SC (OFF_RS + 512)             // 73472
#define SMEM4  (OFF_SC + 512)             // 73984

__global__ void __launch_bounds__(256, 1)
k_main(const float* __restrict__ x, float* __restrict__ out,
       const float* __restrict__ dtp) {
    extern __shared__ __align__(16) unsigned char sm[];
    const unsigned smb = smem_u32(sm);

    const int tid = threadIdx.x;
    const int nb = blockIdx.x, b = blockIdx.y;
    const int w = tid >> 5, lane = tid & 31;
    const int g = lane >> 2, q = lane & 3;

    const __half* Yg = g_y + (size_t)b * FF * NN;
    const __half* Zg = g_zh + (size_t)b * NN * LL;
    const float* cg = g_c + (size_t)b * NN;
    const float* sg = g_sqs + (size_t)b * NN;

    grid_dep_wait();

    // zn tile (128 rows x 16 halves, pitch 48B) -> shares group with fill(0)
    {
        const __half* zsrc = Zg + (size_t)(nb * 128) * LL;
        const int row = tid >> 1, part = tid & 1;
        cp_async16s(smb + OFF_ZN + row * 48 + part * 16, zsrc + row * LL + part * 8);
    }

    auto fill = [&](int t, int st) {
        const unsigned yS = smb + st * ST4;
        const unsigned zmS = yS + YB;
        const unsigned csS = zmS + ZMB;
        for (int i = tid; i < 1024; i += 256)
            cp_async16s(yS + (i >> 2) * 80 + (i & 3) * 16,
                        Yg + (size_t)(i >> 2) * NN + t * 32 + (i & 3) * 8);
        if (tid < 64)
            cp_async16s(zmS + (tid >> 1) * 48 + (tid & 1) * 16,
                        Zg + (size_t)(t * 32 + (tid >> 1)) * LL + (tid & 1) * 8);
        else if (tid < 72)
            cp_async16s(csS + (tid - 64) * 16, cg + t * 32 + (tid - 64) * 4);
        else if (tid < 80)
            cp_async16s(csS + 128 + (tid - 72) * 16, sg + t * 32 + (tid - 72) * 4);
        cp_commit();
    };

    fill(0, 0);
    fill(1, 1);

    const float sqn0 = sg[nb * 128 + w * 16 + g];
    const float sqn1 = sg[nb * 128 + w * 16 + g + 8];
    const float TWOL2E = 2.0f * NL2E;

    float acc[32][4];
#pragma unroll
    for (int nf = 0; nf < 32; nf++) {
        acc[nf][0] = acc[nf][1] = acc[nf][2] = acc[nf][3] = 0.f;
    }
    float rs0 = 0.f, rs1 = 0.f;
    uint32_t znf[4];

    const int b_row = (lane & 7) + ((lane >> 4) << 3);
    const int b_kof = ((lane >> 3) & 1) << 3;

    for (int t = 0; t < KTILES; t++) {
        const int st = t % NST;
        if (t < KTILES - 1) cp_wait1(); else cp_wait0();
        __syncthreads();
        if (t + 2 < KTILES) fill(t + 2, (t + 2) % NST);

        const unsigned yA = smb + st * ST4;
        const unsigned char* zmP = sm + st * ST4 + YB;
        const float* cmS = reinterpret_cast<const float*>(sm + st * ST4 + YB + ZMB);
        const float* sqmS = cmS + 32;

        if (t == 0) {   // zn fragments (ready after first wait)
            const unsigned char* znP = sm + OFF_ZN;
            znf[0] = *reinterpret_cast<const uint32_t*>(znP + (w * 16 + g) * 48 + 4 * q);
            znf[1] = *reinterpret_cast<const uint32_t*>(znP + (w * 16 + g + 8) * 48 + 4 * q);
            znf[2] = *reinterpret_cast<const uint32_t*>(znP + (w * 16 + g) * 48 + 16 + 4 * q);
            znf[3] = *reinterpret_cast<const uint32_t*>(znP + (w * 16 + g + 8) * 48 + 16 + 4 * q);
        }

        // ---- Gram + ex2: K fragments in registers ----
        uint32_t h[4][2];
#pragma unroll
        for (int cf = 0; cf < 4; cf++) {
            float ga[4];
            ga[0] = ga[1] = ga[2] = ga[3] = 0.f;
            uint32_t bf[2];
            bf[0] = *reinterpret_cast<const uint32_t*>(zmP + (cf * 8 + g) * 48 + 4 * q);
            bf[1] = *reinterpret_cast<const uint32_t*>(zmP + (cf * 8 + g) * 48 + 16 + 4 * q);
            mma16816(ga, znf, bf);

            const int c0 = cf * 8 + 2 * q;
            float2 sqc = *reinterpret_cast<const float2*>(&sqmS[c0]);
            h[cf][0] = ex2_f16x2(packh2(
                fminf(fmaf(TWOL2E, ga[0], sqn0 + sqc.x), 0.f),
                fminf(fmaf(TWOL2E, ga[1], sqn0 + sqc.y), 0.f)));
            h[cf][1] = ex2_f16x2(packh2(
                fminf(fmaf(TWOL2E, ga[2], sqn1 + sqc.x), 0.f),
                fminf(fmaf(TWOL2E, ga[3], sqn1 + sqc.y), 0.f)));

            float2 cm2 = *reinterpret_cast<const float2*>(&cmS[c0]);
            __half2 hv0 = *reinterpret_cast<__half2*>(&h[cf][0]);
            __half2 hv1 = *reinterpret_cast<__half2*>(&h[cf][1]);
            float2 f0 = __half22float2(hv0);
            float2 f1 = __half22float2(hv1);
            rs0 = fmaf(f0.x, cm2.x, fmaf(f0.y, cm2.y, rs0));
            rs1 = fmaf(f1.x, cm2.x, fmaf(f1.y, cm2.y, rs1));
        }

        // ---- main MMA: A = K fragments (registers), B = y smem ----
#pragma unroll
        for (int ksI = 0; ksI < 2; ksI++) {
            uint32_t a4[4];
            a4[0] = h[2 * ksI][0];
            a4[1] = h[2 * ksI][1];
            a4[2] = h[2 * ksI + 1][0];
            a4[3] = h[2 * ksI + 1][1];
            const int k0 = ksI * 16;
#pragma unroll
            for (int np = 0; np < 16; np++) {
                uint32_t r4[4];
                ldsm4(r4, yA + ((b_row + np * 16) * KAPITCH + k0 + b_kof) * 2);
                mma16816(acc[2 * np], a4, r4);
                mma16816(acc[2 * np + 1], a4, r4 + 2);
            }
        }
    }

    // rowsum reduce (each row owned by one warp, lanes q=0..3)
    rs0 += __shfl_xor_sync(0xffffffffu, rs0, 1);
    rs0 += __shfl_xor_sync(0xffffffffu, rs0, 2);
    rs1 += __shfl_xor_sync(0xffffffffu, rs1, 1);
    rs1 += __shfl_xor_sync(0xffffffffu, rs1, 2);
    __syncthreads();
    float* rsS = reinterpret_cast<float*>(sm + OFF_RS);
    if (q == 0) { rsS[w * 16 + g] = rs0; rsS[w * 16 + g + 8] = rs1; }
    __syncthreads();
    const float dtv = dtp[0];
    if (tid < 128) {
        float row = rsS[tid] + 1e-5f;
        reinterpret_cast<float*>(sm + OFF_SC)[tid] = (dtv / EPSV) / row;
    }
    __syncthreads();

    const float omdt = 1.0f - dtv;
    const float* scS = reinterpret_cast<const float*>(sm + OFF_SC);
    const float sc0 = scS[w * 16 + g];
    const float sc1 = scS[w * 16 + g + 8];
    const size_t r1 = ((size_t)b * NN + nb * 128 + w * 16 + g) * FF;
    const size_t r2 = r1 + (size_t)8 * FF;
#pragma unroll
    for (int nf = 0; nf < 32; nf++) {
        const int col = nf * 8 + 2 * q;
        float2 x1 = *reinterpret_cast<const float2*>(x + r1 + col);
        float2 x2 = *reinterpret_cast<const float2*>(x + r2 + col);
        float2 o1, o2;
        o1.x = omdt * x1.x + sc0 * acc[nf][0];
        o1.y = omdt * x1.y + sc0 * acc[nf][1];
        o2.x = omdt * x2.x + sc1 * acc[nf][2];
        o2.y = omdt * x2.y + sc1 * acc[nf][3];
        *reinterpret_cast<float2*>(out + r1 + col) = o1;
        *reinterpret_cast<float2*>(out + r2 + col) = o2;
    }
}

// =====================================================================
// launch — PDL chain: k_zpi -> k_q -> k_y -> k_main
// =====================================================================
extern "C" void kernel_launch(void* const* d_in, const int* in_sizes, int n_in,
                              void* d_out, int out_size) {
    const float* x  = (const float*)d_in[0];
    const float* pw = (const float*)d_in[1];
    const float* pb = (const float*)d_in[2];
    const float* w1 = (const float*)d_in[3];
    const float* b1 = (const float*)d_in[4];
    const float* w2 = (const float*)d_in[5];
    const float* b2 = (const float*)d_in[6];
    const float* dt = (const float*)d_in[7];
    float* out = (float*)d_out;

    (void)in_sizes; (void)n_in; (void)out_size;

    const int npts = BB * NN;

    cudaFuncSetAttribute(k_main, cudaFuncAttributeMaxDynamicSharedMemorySize, (int)SMEM4);

    k_zpi<<<npts / 16, 256>>>(x, pw, pb, w1, b1, w2, b2);

    cudaLaunchAttribute at[1];
    at[0].id = cudaLaunchAttributeProgrammaticStreamSerialization;
    at[0].val.programmaticStreamSerializationAllowed = 1;

    cudaLaunchConfig_t cfg;
    memset(&cfg, 0, sizeof(cfg));
    cfg.blockDim = dim3(256, 1, 1);
    cfg.attrs = at;
    cfg.numAttrs = 1;
    cfg.stream = 0;

    cfg.gridDim = dim3(NPAIRS, BB, 1);
    cfg.dynamicSmemBytes = 0;
    cudaLaunchKernelEx(&cfg, k_q);

    cfg.gridDim = dim3(YT, BB, 1);
    cfg.dynamicSmemBytes = 0;
    cudaLaunchKernelEx(&cfg, k_y, x);

    cfg.gridDim = dim3(NN / 128, BB, 1);
    cfg.dynamicSmemBytes = SMEM4;
    cudaLaunchKernelEx(&cfg, k_main, x, out, dt);
}